// round 8
// baseline (speedup 1.0000x reference)
#include <cuda_runtime.h>
#include <math.h>
#include <stdint.h>

#define B_TOT   4096
#define NSEQ    64
#define CDIM    192
#define NH      6
#define NW      64
#define CPBH    512
#define NTHREADS 768

// Shared memory (floats), all XOR-swizzled, no padding:
#define SXS 192
#define SLS 96
#define SXH_OFF 0
#define SAL_OFF (SXH_OFF + 64*SXS)
#define SQ_OFF  (SAL_OFF + 64*SLS)
#define SK_OFF  (SQ_OFF + NH*64*32)
#define SV_OFF  (SK_OFF + NH*64*32)
#define SSC_OFF (SV_OFF + NH*64*32)
#define SMEM_FLOATS (SSC_OFF + 8)
#define SMEM_BYTES (SMEM_FLOATS * 4)

__device__ float g_bias[NH * NSEQ * NSEQ];
__device__ float g_bm[(size_t)NW * NH * NSEQ * NSEQ];

// Weight tables: (ng, ks, nt, lane) -> uint4(tf32 bh0, tf32 bh1, bf16x2 blo, bf16x2 bhi)
#define QKV_TBL (6*24*12*32)
#define PRJ_TBL (6*24*4*32)
__device__ uint4 g_wq[QKV_TBL];
__device__ uint4 g_wp[PRJ_TBL];

__device__ __forceinline__ uint32_t f2tf(float f) {
    uint32_t u; asm("cvt.rna.tf32.f32 %0, %1;" : "=r"(u) : "f"(f)); return u;
}
__device__ __forceinline__ float f2tff(float f) { return __uint_as_float(f2tf(f)); }
__device__ __forceinline__ uint32_t packbf(float hi, float lo) {
    uint32_t r; asm("cvt.rn.bf16x2.f32 %0, %1, %2;" : "=r"(r) : "f"(hi), "f"(lo)); return r;
}
__device__ __forceinline__ void mma8(float* d, const uint32_t* a, uint32_t b0, uint32_t b1) {
    asm volatile("mma.sync.aligned.m16n8k8.row.col.f32.tf32.tf32.f32 "
                 "{%0,%1,%2,%3},{%4,%5,%6,%7},{%8,%9},{%0,%1,%2,%3};"
                 : "+f"(d[0]), "+f"(d[1]), "+f"(d[2]), "+f"(d[3])
                 : "r"(a[0]), "r"(a[1]), "r"(a[2]), "r"(a[3]), "r"(b0), "r"(b1));
}
__device__ __forceinline__ void mma16bf(float* d, const uint32_t* a, uint32_t b0, uint32_t b1) {
    asm volatile("mma.sync.aligned.m16n8k16.row.col.f32.bf16.bf16.f32 "
                 "{%0,%1,%2,%3},{%4,%5,%6,%7},{%8,%9},{%0,%1,%2,%3};"
                 : "+f"(d[0]), "+f"(d[1]), "+f"(d[2]), "+f"(d[3])
                 : "r"(a[0]), "r"(a[1]), "r"(a[2]), "r"(a[3]), "r"(b0), "r"(b1));
}
__device__ __forceinline__ void tfsplit(float v, uint32_t& hi, uint32_t& lo) {
    hi = f2tf(v);
    lo = f2tf(v - __uint_as_float(hi));
}

// ---------------------------------------------------------------------------
__global__ void prep_w_kernel(const float* __restrict__ qkv_w,
                              const float* __restrict__ proj_w)
{
    int i = blockIdx.x * blockDim.x + threadIdx.x;
    const float* w; uint4* dst; int NT, idx;
    if (i < QKV_TBL)                { w = qkv_w;  dst = g_wq; NT = 12; idx = i; }
    else if (i < QKV_TBL + PRJ_TBL) { w = proj_w; dst = g_wp; NT = 4;  idx = i - QKV_TBL; }
    else return;

    int lane = idx & 31, r = idx >> 5;
    int nt = r % NT; r /= NT;
    int ks = r % 24; int ng = r / 24;
    int g = lane >> 2, qd = lane & 3;
    int col = ng * (NT * 8) + nt * 8 + g;
    const float* wr = &w[col * 192 + ks * 8];

    uint32_t bh0 = f2tf(wr[qd]);
    uint32_t bh1 = f2tf(wr[qd + 4]);
    float e0 = wr[2 * qd], e1 = wr[2 * qd + 1];
    uint32_t blo = packbf(e1 - f2tff(e1), e0 - f2tff(e0));
    uint32_t bhi = packbf(e1, e0);
    dst[idx] = make_uint4(bh0, bh1, blo, bhi);
}

// ---------------------------------------------------------------------------
__global__ void cpb_kernel(const float* __restrict__ w1,
                           const float* __restrict__ b1,
                           const float* __restrict__ w2)
{
    __shared__ float rpb[225 * NH];
    const int t = threadIdx.x;
    const float inv_log2_8 = 1.0f / 3.0f;

    for (int e = t; e < 225 * NH; e += 256) {
        int te = e / NH, h = e % NH;
        int i = te / 15, j = te % 15;
        float cy = (float)(i - 7) * (8.0f / 7.0f);
        float cx = (float)(j - 7) * (8.0f / 7.0f);
        cy = copysignf(log2f(fabsf(cy) + 1.0f), cy) * inv_log2_8;
        cx = copysignf(log2f(fabsf(cx) + 1.0f), cx) * inv_log2_8;
        float acc = 0.0f;
        for (int k = 0; k < CPBH; k++) {
            float hm = fmaxf(cy * w1[2 * k] + cx * w1[2 * k + 1] + b1[k], 0.0f);
            acc += hm * w2[h * CPBH + k];
        }
        rpb[te * NH + h] = acc;
    }
    __syncthreads();

    for (int e = t; e < NH * NSEQ * NSEQ; e += 256) {
        int h = e / (NSEQ * NSEQ);
        int rr = e % (NSEQ * NSEQ);
        int i = rr / NSEQ, j = rr % NSEQ;
        int dy = (i >> 3) - (j >> 3) + 7;
        int dx = (i & 7) - (j & 7) + 7;
        g_bias[e] = 16.0f / (1.0f + expf(-rpb[(dy * 15 + dx) * NH + h]));
    }
}

__global__ void bm_kernel(const float* __restrict__ mask)
{
    int blk = blockIdx.x;            // widx*NH + h
    int widx = blk / NH, h = blk % NH;
    const float* mrow = mask + (size_t)widx * NSEQ * NSEQ;
    const float* brow = g_bias + h * NSEQ * NSEQ;
    float* dst = g_bm + (size_t)blk * NSEQ * NSEQ;
    for (int i = threadIdx.x; i < NSEQ * NSEQ; i += 256)
        dst[i] = brow[i] + mrow[i];
}

// ---------------------------------------------------------------------------
__global__ __launch_bounds__(NTHREADS, 1)
void win_attn_kernel(const float* __restrict__ x,
                     const float* __restrict__ q_bias,
                     const float* __restrict__ v_bias,
                     const float* __restrict__ logit_scale,
                     const float* __restrict__ proj_b,
                     float* __restrict__ out)
{
    extern __shared__ float sm[];
    float*    sxh = sm + SXH_OFF;
    uint32_t* sal = (uint32_t*)(sm + SAL_OFF);
    float*    sq  = sm + SQ_OFF;
    float*    sk  = sm + SK_OFF;
    float*    sv  = sm + SV_OFF;
    float*    sscale = sm + SSC_OFF;

    const int t = threadIdx.x;
    const int b = blockIdx.x;
    const int widx = b & (NW - 1);
    const float* xb = x + (size_t)b * NSEQ * CDIM;

    const int w    = t >> 5;
    const int lane = t & 31;
    const int g    = lane >> 2;
    const int qd   = lane & 3;
    const int swg  = g << 2;

    // -------- load x: tf32-hi (f32, swizzled) + packed bf16 lo --------
    for (int idx = t; idx < NSEQ * CDIM / 4; idx += NTHREADS) {
        float4 v4 = ((const float4*)xb)[idx];
        int n = (idx * 4) / CDIM;
        int k = (idx * 4) % CDIM;
        int sw = (n & 7) << 2;
        float h0 = f2tff(v4.x), h1 = f2tff(v4.y), h2 = f2tff(v4.z), h3 = f2tff(v4.w);
        *(float4*)&sxh[n * SXS + (k ^ sw)] = make_float4(h0, h1, h2, h3);
        uint32_t u0 = packbf(v4.y - h1, v4.x - h0);
        uint32_t u1 = packbf(v4.w - h3, v4.z - h2);
        *(uint2*)&sal[n * SLS + ((k >> 1) ^ sw)] = make_uint2(u0, u1);
    }
    if (t < NH) sscale[t] = __expf(fminf(logit_scale[t], 4.60517019f)); // ln(100)
    __syncthreads();

    // ============ Phase 1: QKV GEMM; warp = 1 m16 tile x 96 cols ============
    {
        const int mt4 = w & 3;         // row group (16 rows)
        const int ng  = w >> 2;        // 0..5 col group (96 cols)
        const int r0  = mt4 * 16 + g;

        float acc[12][4];
        #pragma unroll
        for (int nt = 0; nt < 12; nt++)
            #pragma unroll
            for (int e = 0; e < 4; e++) acc[nt][e] = 0.0f;

        const uint4* wtab = &g_wq[(ng * 24 * 12) * 32 + lane];

        for (int ks = 0; ks < 24; ks++) {
            int k0 = ks * 8;
            uint32_t ah[4], ac[4];
            {
                const float* X0 = &sxh[r0 * SXS];
                const float* X8 = X0 + 8 * SXS;
                int cA = (k0 + qd) ^ swg, cB = (k0 + qd + 4) ^ swg;
                ah[0] = __float_as_uint(X0[cA]);
                ah[1] = __float_as_uint(X8[cA]);
                ah[2] = __float_as_uint(X0[cB]);
                ah[3] = __float_as_uint(X8[cB]);
                int cC = (k0 + 2 * qd) ^ swg;
                float2 p0 = *(const float2*)&X0[cC];
                float2 p8 = *(const float2*)&X8[cC];
                ac[0] = packbf(p0.y, p0.x);
                ac[1] = packbf(p8.y, p8.x);
                int cU = ((k0 >> 1) + qd) ^ swg;
                ac[2] = sal[r0 * SLS + cU];
                ac[3] = sal[(r0 + 8) * SLS + cU];
            }
            const uint4* wrow = wtab + (ks * 12) * 32;
            #pragma unroll
            for (int nt = 0; nt < 12; nt++) {
                uint4 bb = wrow[nt * 32];
                mma8(acc[nt], ah, bb.x, bb.y);
                mma16bf(acc[nt], ac, bb.z, bb.w);
            }
        }

        // ---- norms then scatter with folded scales ----
        const int s = ng >> 1;   // 0=q, 1=k, 2=v
        float inv[2][3];
        if (s < 2) {
            float ssq[2][3];
            #pragma unroll
            for (int c = 0; c < 2; c++)
                #pragma unroll
                for (int hh = 0; hh < 3; hh++) ssq[c][hh] = 0.0f;
            #pragma unroll
            for (int nt = 0; nt < 12; nt++) {
                int rem = ng * 96 + nt * 8 + qd * 2 - s * 192;
                #pragma unroll
                for (int rr = 0; rr < 2; rr++) {
                    float v0 = acc[nt][rr * 2 + 0];
                    float v1 = acc[nt][rr * 2 + 1];
                    if (s == 0) { v0 += q_bias[rem]; v1 += q_bias[rem + 1]; }
                    ssq[rr][nt >> 2] += v0 * v0 + v1 * v1;
                }
            }
            #pragma unroll
            for (int rr = 0; rr < 2; rr++)
                #pragma unroll
                for (int hs = 0; hs < 3; hs++) {
                    float tot = ssq[rr][hs];
                    tot += __shfl_xor_sync(0xffffffffu, tot, 1);
                    tot += __shfl_xor_sync(0xffffffffu, tot, 2);
                    float sc = (s == 0) ? sscale[(ng & 1) * 3 + hs] : 1.0f;
                    inv[rr][hs] = sc / fmaxf(sqrtf(tot), 1e-12f);
                }
        }

        #pragma unroll
        for (int nt = 0; nt < 12; nt++) {
            int rem = ng * 96 + nt * 8 + qd * 2 - s * 192;
            int h = rem >> 5, d = rem & 31;
            #pragma unroll
            for (int rr = 0; rr < 2; rr++) {
                int n = mt4 * 16 + g + rr * 8;
                float v0 = acc[nt][rr * 2 + 0];
                float v1 = acc[nt][rr * 2 + 1];
                if (s == 0) {
                    float iv = inv[rr][nt >> 2];
                    *(float2*)&sq[(h * 64 + n) * 32 + (d ^ swg)] =
                        make_float2((v0 + q_bias[rem]) * iv, (v1 + q_bias[rem + 1]) * iv);
                } else if (s == 1) {
                    float iv = inv[rr][nt >> 2];
                    *(float2*)&sk[(h * 64 + n) * 32 + (d ^ swg)] =
                        make_float2(v0 * iv, v1 * iv);
                } else {
                    *(float2*)&sv[(h * 64 + n) * 32 + (d ^ ((g & 3) << 3))] =
                        make_float2(v0 + v_bias[rem], v1 + v_bias[rem + 1]);
                }
            }
        }
    }
    __syncthreads();

    // ============ Phase 2: attention; warp = 1 head x 1 m16 row tile =======
    {
        const int h  = w >> 2;
        const int m0 = (w & 3) * 16;

        float p[8][4];
        #pragma unroll
        for (int nt = 0; nt < 8; nt++)
            #pragma unroll
            for (int e = 0; e < 4; e++) p[nt][e] = 0.0f;

        #pragma unroll
        for (int kt = 0; kt < 4; kt++) {
            int cA = (kt * 8 + qd) ^ swg, cB = (kt * 8 + qd + 4) ^ swg;
            uint32_t ahi[4], alo[4];
            {
                const float* Q0 = &sq[(h * 64 + m0 + g) * 32];
                const float* Q8 = Q0 + 8 * 32;
                tfsplit(Q0[cA], ahi[0], alo[0]);
                tfsplit(Q8[cA], ahi[1], alo[1]);
                tfsplit(Q0[cB], ahi[2], alo[2]);
                tfsplit(Q8[cB], ahi[3], alo[3]);
            }
            #pragma unroll
            for (int nt = 0; nt < 8; nt++) {
                const float* K0 = &sk[(h * 64 + nt * 8 + g) * 32];
                uint32_t bh0, bl0, bh1, bl1;
                tfsplit(K0[cA], bh0, bl0);
                tfsplit(K0[cB], bh1, bl1);
                mma8(p[nt], ahi, bh0, bh1);
                mma8(p[nt], ahi, bl0, bl1);
                mma8(p[nt], alo, bh0, bh1);
            }
        }

        // ---- bias+mask, softmax ----
        const float* bmb = &g_bm[((size_t)widx * NH + h) * NSEQ * NSEQ];
        #pragma unroll
        for (int r2 = 0; r2 < 2; r2++) {
            int row = m0 + g + 8 * r2;
            const float* bmr = bmb + row * 64 + qd * 2;
            float mx = -1e30f;
            #pragma unroll
            for (int nt = 0; nt < 8; nt++) {
                float2 bmv = *(const float2*)&bmr[nt * 8];
                p[nt][r2 * 2 + 0] += bmv.x;
                p[nt][r2 * 2 + 1] += bmv.y;
                mx = fmaxf(mx, fmaxf(p[nt][r2 * 2], p[nt][r2 * 2 + 1]));
            }
            mx = fmaxf(mx, __shfl_xor_sync(0xffffffffu, mx, 1));
            mx = fmaxf(mx, __shfl_xor_sync(0xffffffffu, mx, 2));
            float sum = 0.0f;
            #pragma unroll
            for (int nt = 0; nt < 8; nt++) {
                float e0 = __expf(p[nt][r2 * 2 + 0] - mx);
                float e1 = __expf(p[nt][r2 * 2 + 1] - mx);
                p[nt][r2 * 2 + 0] = e0;
                p[nt][r2 * 2 + 1] = e1;
                sum += e0 + e1;
            }
            sum += __shfl_xor_sync(0xffffffffu, sum, 1);
            sum += __shfl_xor_sync(0xffffffffu, sum, 2);
            float rs = 1.0f / sum;
            #pragma unroll
            for (int nt = 0; nt < 8; nt++) {
                p[nt][r2 * 2 + 0] *= rs;
                p[nt][r2 * 2 + 1] *= rs;
            }
        }

        // ---- PV ----
        float o[4][4];
        #pragma unroll
        for (int nt = 0; nt < 4; nt++)
            #pragma unroll
            for (int e = 0; e < 4; e++) o[nt][e] = 0.0f;

        const int s0 = g * 4 + (qd >> 1);
        const int s1 = s0 + 2;
        const bool odd = (qd & 1);

        #pragma unroll
        for (int kt = 0; kt < 8; kt++) {
            uint32_t phi[4], plo[4];
            {
                float e0 = __shfl_sync(0xffffffffu, p[kt][0], s0);
                float e1 = __shfl_sync(0xffffffffu, p[kt][1], s0);
                float e2 = __shfl_sync(0xffffffffu, p[kt][2], s0);
                float e3 = __shfl_sync(0xffffffffu, p[kt][3], s0);
                float f0 = __shfl_sync(0xffffffffu, p[kt][0], s1);
                float f1 = __shfl_sync(0xffffffffu, p[kt][1], s1);
                float f2 = __shfl_sync(0xffffffffu, p[kt][2], s1);
                float f3 = __shfl_sync(0xffffffffu, p[kt][3], s1);
                tfsplit(odd ? e1 : e0, phi[0], plo[0]);
                tfsplit(odd ? e3 : e2, phi[1], plo[1]);
                tfsplit(odd ? f1 : f0, phi[2], plo[2]);
                tfsplit(odd ? f3 : f2, phi[3], plo[3]);
            }
            #pragma unroll
            for (int nt = 0; nt < 4; nt++) {
                int cv = (nt * 8 + g) ^ (qd << 3);
                float v0 = sv[(h * 64 + kt * 8 + qd) * 32 + cv];
                float v1 = sv[(h * 64 + kt * 8 + qd + 4) * 32 + cv];
                uint32_t vh0, vl0, vh1, vl1;
                tfsplit(v0, vh0, vl0);
                tfsplit(v1, vh1, vl1);
                mma8(o[nt], phi, vh0, vh1);
                mma8(o[nt], phi, vl0, vl1);
                mma8(o[nt], plo, vh0, vh1);
            }
        }

        // ---- write attn output as hi + packed lo (swizzled) ----
        #pragma unroll
        for (int nt = 0; nt < 4; nt++) {
            int col0 = h * 32 + nt * 8 + qd * 2;
            #pragma unroll
            for (int r2 = 0; r2 < 2; r2++) {
                int row = m0 + g + 8 * r2;
                float o0 = o[nt][r2 * 2 + 0];
                float o1 = o[nt][r2 * 2 + 1];
                float h0 = f2tff(o0), h1 = f2tff(o1);
                *(float2*)&sxh[row * SXS + (col0 ^ swg)] = make_float2(h0, h1);
                sal[row * SLS + ((col0 >> 1) ^ swg)] = packbf(o1 - h1, o0 - h0);
            }
        }
    }
    __syncthreads();

    // ============ Phase 3: proj GEMM; warp = 1 m16 tile x 32 cols ==========
    {
        const int mt4 = w & 3;
        const int ng  = w >> 2;
        const int r0  = mt4 * 16 + g;

        float acc[4][4];
        #pragma unroll
        for (int nt = 0; nt < 4; nt++)
            #pragma unroll
            for (int e = 0; e < 4; e++) acc[nt][e] = 0.0f;

        const uint4* wtab = &g_wp[(ng * 24 * 4) * 32 + lane];

        for (int ks = 0; ks < 24; ks++) {
            int k0 = ks * 8;
            uint32_t ah[4], ac[4];
            {
                const float* X0 = &sxh[r0 * SXS];
                const float* X8 = X0 + 8 * SXS;
                int cA = (k0 + qd) ^ swg, cB = (k0 + qd + 4) ^ swg;
                ah[0] = __float_as_uint(X0[cA]);
                ah[1] = __float_as_uint(X8[cA]);
                ah[2] = __float_as_uint(X0[cB]);
                ah[3] = __float_as_uint(X8[cB]);
                int cC = (k0 + 2 * qd) ^ swg;
                float2 p0 = *(const float2*)&X0[cC];
                float2 p8 = *(const float2*)&X8[cC];
                ac[0] = packbf(p0.y, p0.x);
                ac[1] = packbf(p8.y, p8.x);
                int cU = ((k0 >> 1) + qd) ^ swg;
                ac[2] = sal[r0 * SLS + cU];
                ac[3] = sal[(r0 + 8) * SLS + cU];
            }
            const uint4* wrow = wtab + (ks * 4) * 32;
            #pragma unroll
            for (int nt = 0; nt < 4; nt++) {
                uint4 bb = wrow[nt * 32];
                mma8(acc[nt], ah, bb.x, bb.y);
                mma16bf(acc[nt], ac, bb.z, bb.w);
            }
        }

        float* ob = out + (size_t)b * NSEQ * CDIM;
        #pragma unroll
        for (int nt = 0; nt < 4; nt++) {
            int col0 = ng * 32 + nt * 8 + qd * 2;
            float pb0 = proj_b[col0], pb1 = proj_b[col0 + 1];
            #pragma unroll
            for (int rr = 0; rr < 2; rr++) {
                int n = mt4 * 16 + g + rr * 8;
                *(float2*)&ob[n * 192 + col0] =
                    make_float2(acc[nt][rr * 2 + 0] + pb0,
                                acc[nt][rr * 2 + 1] + pb1);
            }
        }
    }
}

// ---------------------------------------------------------------------------
extern "C" void kernel_launch(void* const* d_in, const int* in_sizes, int n_in,
                              void* d_out, int out_size)
{
    const float* x           = (const float*)d_in[0];
    const float* mask        = (const float*)d_in[1];
    const float* qkv_w       = (const float*)d_in[2];
    const float* q_bias      = (const float*)d_in[3];
    const float* v_bias      = (const float*)d_in[4];
    const float* logit_scale = (const float*)d_in[5];
    const float* cpb_w1      = (const float*)d_in[6];
    const float* cpb_b1      = (const float*)d_in[7];
    const float* cpb_w2      = (const float*)d_in[8];
    const float* proj_w      = (const float*)d_in[9];
    const float* proj_b      = (const float*)d_in[10];
    float* out = (float*)d_out;

    cudaFuncSetAttribute(win_attn_kernel,
                         cudaFuncAttributeMaxDynamicSharedMemorySize, SMEM_BYTES);

    prep_w_kernel<<<(QKV_TBL + PRJ_TBL + 255) / 256, 256>>>(qkv_w, proj_w);
    cpb_kernel<<<1, 256>>>(cpb_w1, cpb_b1, cpb_w2);
    bm_kernel<<<NW * NH, 256>>>(mask);
    win_attn_kernel<<<B_TOT, NTHREADS, SMEM_BYTES>>>(
        x, q_bias, v_bias, logit_scale, proj_b, out);
}